// round 7
// baseline (speedup 1.0000x reference)
#include <cuda_runtime.h>
#include <cuda_bf16.h>
#include <cstdint>

#define B_DIM 4096
#define N_CIT 16
#define D_IN  1024
#define D_OUT 1024
#define KTOT  (N_CIT * D_IN)       /* 16384 */
#define EPSV  0.01f

// ---------------- scratch (static device arrays; no cudaMalloc) -------------
__device__ float g_logits[B_DIM * 256];
__device__ float g_power [B_DIM * 16];
__device__ __nv_bfloat16 g_wt_hi[(size_t)D_OUT * KTOT];  // [o][k] K-major
__device__ __nv_bfloat16 g_wt_lo[(size_t)D_OUT * KTOT];
__device__ __nv_bfloat16 g_by_hi[(size_t)D_OUT * 64];    // [o][k] k 0..15 real, rest 0
__device__ __nv_bfloat16 g_by_lo[(size_t)D_OUT * 64];

// ---------------- helpers ----------------------------------------------------
__device__ __forceinline__ uint32_t smem_to_u32(const void* p) {
    uint32_t a;
    asm("{ .reg .u64 t; cvta.to.shared.u64 t, %1; cvt.u32.u64 %0, t; }" : "=r"(a) : "l"(p));
    return a;
}

// swizzled address in a tile of 128B rows: granule q (0..7), 16B each
__device__ __forceinline__ uint32_t sw128(uint32_t base, int row, int q) {
    return base + row * 128 + (((uint32_t)(q ^ (row & 7))) << 4);
}

// pack two floats as bf16x2 (f0 -> low half)
__device__ __forceinline__ uint32_t pack_bf16(float f0, float f1) {
    uint32_t r;
    asm("cvt.rn.bf16x2.f32 %0, %1, %2;" : "=r"(r) : "f"(f1), "f"(f0));
    return r;
}

#define CP_ASYNC16(dst, src) \
    asm volatile("cp.async.cg.shared.global [%0], [%1], 16;" :: "r"(dst), "l"(src) : "memory")
#define CP_COMMIT() asm volatile("cp.async.commit_group;" ::: "memory")
#define CP_WAIT0()  asm volatile("cp.async.wait_group 0;" ::: "memory")

#define LDSM4(r, addr) \
    asm volatile("ldmatrix.sync.aligned.m8n8.x4.shared.b16 {%0,%1,%2,%3}, [%4];" \
        : "=r"((r)[0]), "=r"((r)[1]), "=r"((r)[2]), "=r"((r)[3]) : "r"(addr))

#define MMA_BF16(d, a, b) \
    asm volatile("mma.sync.aligned.m16n8k16.row.col.f32.bf16.bf16.f32 " \
        "{%0,%1,%2,%3}, {%4,%5,%6,%7}, {%8,%9}, {%0,%1,%2,%3};" \
        : "+f"((d)[0]), "+f"((d)[1]), "+f"((d)[2]), "+f"((d)[3]) \
        : "r"((a)[0]), "r"((a)[1]), "r"((a)[2]), "r"((a)[3]), "r"((b)[0]), "r"((b)[1]))

#define STS128(addr, r0, r1, r2, r3) \
    asm volatile("st.shared.v4.b32 [%0], {%1,%2,%3,%4};" \
        :: "r"(addr), "r"(r0), "r"(r1), "r"(r2), "r"(r3) : "memory")

// ============================================================================
// Kernel 0a: transpose + hi/lo bf16 split: Wy[16384,1024] -> g_wt[1024][16384]
// ============================================================================
__global__ __launch_bounds__(256) void transpose_split(const float* __restrict__ Wy)
{
    __shared__ float T[64][65];
    const int k0 = blockIdx.x * 64;
    const int o0 = blockIdx.y * 64;
    const int tid = threadIdx.x;

    {
        int kr = tid >> 4, o4 = tid & 15;
        #pragma unroll
        for (int r = 0; r < 4; r++) {
            int k = kr + r * 16;
            float4 v = *(const float4*)&Wy[(size_t)(k0 + k) * D_OUT + o0 + o4 * 4];
            T[k][o4 * 4 + 0] = v.x;  T[k][o4 * 4 + 1] = v.y;
            T[k][o4 * 4 + 2] = v.z;  T[k][o4 * 4 + 3] = v.w;
        }
    }
    __syncthreads();

    {
        int o = tid >> 2, kq = tid & 3;
        uint32_t hi[8], lo[8];
        #pragma unroll
        for (int i = 0; i < 8; i++) {
            float a = T[kq * 16 + i * 2][o];
            float b = T[kq * 16 + i * 2 + 1][o];
            uint32_t h = pack_bf16(a, b);
            float fha = __uint_as_float(h << 16);
            float fhb = __uint_as_float(h & 0xFFFF0000u);
            hi[i] = h;
            lo[i] = pack_bf16(a - fha, b - fhb);
        }
        size_t dst = (size_t)(o0 + o) * KTOT + k0 + kq * 16;
        *(uint4*)&g_wt_hi[dst]     = make_uint4(hi[0], hi[1], hi[2], hi[3]);
        *(uint4*)&g_wt_hi[dst + 8] = make_uint4(hi[4], hi[5], hi[6], hi[7]);
        *(uint4*)&g_wt_lo[dst]     = make_uint4(lo[0], lo[1], lo[2], lo[3]);
        *(uint4*)&g_wt_lo[dst + 8] = make_uint4(lo[4], lo[5], lo[6], lo[7]);
    }
}

// ============================================================================
// Kernel 0b: by[16][1024] -> g_by[1024][64] bf16 hi/lo (k 16..63 zero)
// ============================================================================
__global__ __launch_bounds__(256) void by_prep(const float* __restrict__ by)
{
    int o = blockIdx.x * 256 + threadIdx.x;
    if (o >= D_OUT) return;
    #pragma unroll
    for (int kp = 0; kp < 8; kp++) {
        float a = by[(size_t)(kp * 2)     * D_OUT + o];
        float b = by[(size_t)(kp * 2 + 1) * D_OUT + o];
        uint32_t h = pack_bf16(a, b);
        float fha = __uint_as_float(h << 16);
        float fhb = __uint_as_float(h & 0xFFFF0000u);
        uint32_t l = pack_bf16(a - fha, b - fhb);
        *(uint32_t*)&g_by_hi[(size_t)o * 64 + kp * 2] = h;
        *(uint32_t*)&g_by_lo[(size_t)o * 64 + kp * 2] = l;
    }
    #pragma unroll
    for (int kp = 8; kp < 32; kp++) {
        *(uint32_t*)&g_by_hi[(size_t)o * 64 + kp * 2] = 0u;
        *(uint32_t*)&g_by_lo[(size_t)o * 64 + kp * 2] = 0u;
    }
}

// ============================================================================
// Kernel 1: logits
// ============================================================================
__global__ __launch_bounds__(256) void logits_kernel(
    const float* __restrict__ x, const float* __restrict__ Wd,
    const float* __restrict__ bd)
{
    __shared__ float Xs[32][68];
    __shared__ float Ws[32][64];

    const int bm = blockIdx.y * 64;
    const int bc = blockIdx.x * 64;
    const int tid = threadIdx.x;
    const int tx = tid & 15, ty = tid >> 4;

    float acc[4][4] = {};

    for (int k0 = 0; k0 < D_IN; k0 += 32) {
        #pragma unroll
        for (int j = 0; j < 2; j++) {
            int L = tid + j * 256;
            int m = L >> 3, kq = L & 7;
            float4 v = *(const float4*)&x[(size_t)(bm + m) * D_IN + k0 + kq * 4];
            Xs[kq * 4 + 0][m] = v.x;  Xs[kq * 4 + 1][m] = v.y;
            Xs[kq * 4 + 2][m] = v.z;  Xs[kq * 4 + 3][m] = v.w;
        }
        #pragma unroll
        for (int j = 0; j < 2; j++) {
            int L = tid + j * 256;
            int kk = L >> 4, c4 = L & 15;
            int c = bc + c4 * 4;
            int n = c >> 4, jj = c & 15;
            float4 v = *(const float4*)&Wd[(size_t)n * (D_IN * N_CIT) + (size_t)(k0 + kk) * N_CIT + jj];
            *(float4*)&Ws[kk][c4 * 4] = v;
        }
        __syncthreads();
        #pragma unroll
        for (int kk = 0; kk < 32; kk++) {
            float4 a4 = *(const float4*)&Xs[kk][ty * 4];
            float4 b4 = *(const float4*)&Ws[kk][tx * 4];
            float a[4] = {a4.x, a4.y, a4.z, a4.w};
            float b[4] = {b4.x, b4.y, b4.z, b4.w};
            #pragma unroll
            for (int mi = 0; mi < 4; mi++)
                #pragma unroll
                for (int ci = 0; ci < 4; ci++)
                    acc[mi][ci] += a[mi] * b[ci];
        }
        __syncthreads();
    }

    const int cg = bc + tx * 4;
    #pragma unroll
    for (int mi = 0; mi < 4; mi++) {
        int m = bm + ty * 4 + mi;
        float4 r;
        r.x = acc[mi][0] + bd[cg + 0];
        r.y = acc[mi][1] + bd[cg + 1];
        r.z = acc[mi][2] + bd[cg + 2];
        r.w = acc[mi][3] + bd[cg + 3];
        *(float4*)&g_logits[(size_t)m * 256 + cg] = r;
    }
}

// ============================================================================
// Kernel 2: warp-parallel softmax + 16x16 solve. 16 lanes per batch.
// ============================================================================
__global__ __launch_bounds__(256) void power_kernel()
{
    const int tid = threadIdx.x;
    const int lane = tid & 31;
    const int l16 = lane & 15;
    const int b = blockIdx.x * 16 + (tid >> 4);   // 16 batches per block
    const float ome = 1.f - EPSV;

    // --- softmax of this thread's delegation row (row = l16) ---
    float d[16];
    {
        const float* lg = g_logits + (size_t)b * 256 + l16 * 16;
        #pragma unroll
        for (int q = 0; q < 4; q++) {
            float4 t = *(const float4*)(lg + q * 4);
            d[q * 4 + 0] = t.x; d[q * 4 + 1] = t.y;
            d[q * 4 + 2] = t.z; d[q * 4 + 3] = t.w;
        }
        float mx = d[0];
        #pragma unroll
        for (int j = 1; j < 16; j++) mx = fmaxf(mx, d[j]);
        float s = 0.f;
        #pragma unroll
        for (int j = 0; j < 16; j++) { d[j] = expf(d[j] - mx); s += d[j]; }
        float inv = 1.f / s;
        #pragma unroll
        for (int j = 0; j < 16; j++) d[j] *= inv;
    }

    // --- 16x16 register transpose via shfl butterflies ---
    // after: d[n] on lane r == dall[n][r]
    #pragma unroll
    for (int m = 1; m < 16; m <<= 1) {
        float u[16];
        #pragma unroll
        for (int i = 0; i < 16; i++)
            u[i] = __shfl_xor_sync(0xffffffffu, d[i ^ m], m);
        #pragma unroll
        for (int i = 0; i < 16; i++)
            if ((i & m) != (l16 & m)) d[i] = u[i];
    }

    // diag = dall[r][r]  (element l16 of transposed column)
    float diag = 0.f;
    #pragma unroll
    for (int i = 0; i < 16; i++)
        if (i == l16) diag = d[i];

    // --- build row l16 of (I - (1-eps)*D_nodiag):  A[r][n] ---
    float row[17];
    #pragma unroll
    for (int n = 0; n < 16; n++)
        row[n] = (n == l16) ? 1.f : -ome * d[n];
    row[16] = 1.f;

    // --- row-parallel Gaussian elimination (no pivoting; col-dominant) ---
    #pragma unroll
    for (int p = 0; p < 16; p++) {
        float pivot = __shfl_sync(0xffffffffu, row[p], p, 16);
        float inv = 1.f / pivot;
        float f = row[p];
        #pragma unroll
        for (int c = p; c < 17; c++) {
            float pc = __shfl_sync(0xffffffffu, row[c], p, 16) * inv;
            if (l16 == p)      row[c] = pc;
            else if (l16 > p)  row[c] -= f * pc;
        }
    }

    // --- back substitution (diag normalized to 1) ---
    float s = row[16];
    float z = 0.f;
    #pragma unroll
    for (int r = 15; r >= 0; r--) {
        float zr = __shfl_sync(0xffffffffu, s, r, 16);
        if (l16 == r) z = zr;
        if (l16 < r)  s -= row[r] * zr;
    }

    // --- combine ---
    float zs = z;
    #pragma unroll
    for (int m = 8; m >= 1; m >>= 1)
        zs += __shfl_xor_sync(0xffffffffu, zs, m);
    float z16 = 1.f + EPSV * zs;
    float add = z16 * (1.f / 16.f) - (1.f / 16.f);
    g_power[(size_t)b * 16 + l16] = z * ome * diag + add;
}

// ============================================================================
// Kernel 3: mma.sync split-bf16 GEMM. CTA tile 128x256, K-chunk 64, 2 buffers.
// Buffer (96KB): A_hi[16K] A_lo[16K] B_hi[32K] B_lo[32K]
// ============================================================================
#define BUFSTRIDE 98304
#define GSMEM_TOTAL (2 * BUFSTRIDE)
#define NSTG 257

__device__ __forceinline__ void cp_b_stage(uint32_t buf, int bn, int t, int tid)
{
    uint32_t bh = buf + 32768, bl = buf + 65536;
    const char *sh, *sl;
    if (t < 256) {
        size_t off = ((size_t)(bn + tid) * KTOT +
                      (size_t)(t & 15) * 1024 + (size_t)(t >> 4) * 64) * 2;
        sh = (const char*)g_wt_hi + off;
        sl = (const char*)g_wt_lo + off;
    } else {
        size_t off = (size_t)(bn + tid) * 128;
        sh = (const char*)g_by_hi + off;
        sl = (const char*)g_by_lo + off;
    }
    #pragma unroll
    for (int q = 0; q < 8; q++) {
        CP_ASYNC16(sw128(bh, tid, q), sh + q * 16);
        CP_ASYNC16(sw128(bl, tid, q), sl + q * 16);
    }
}

// generate the A tile (hi/lo split of power-scaled x, 128 rows x 64 k) for stage t
__device__ __forceinline__ void gen_a_stage(uint32_t buf, const float* __restrict__ x,
                                            int bm, int t, int tid)
{
    const int ar = tid >> 1;
    const int half = tid & 1;     // which 32-k half of the 64-k chunk
    float v[32];
    float p;
    if (t < 256) {
        const int n = t & 15, o = t >> 4;
        p = g_power[(size_t)(bm + ar) * 16 + n];
        const float* xp = x + (size_t)(bm + ar) * D_IN + o * 64 + half * 32;
        #pragma unroll
        for (int q = 0; q < 8; q++) {
            float4 t4 = *(const float4*)(xp + q * 4);
            v[q * 4 + 0] = t4.x; v[q * 4 + 1] = t4.y;
            v[q * 4 + 2] = t4.z; v[q * 4 + 3] = t4.w;
        }
    } else {
        p = 1.f;
        #pragma unroll
        for (int q = 0; q < 32; q++) v[q] = 0.f;
        if (half == 0) {
            const float* pp = &g_power[(size_t)(bm + ar) * 16];
            #pragma unroll
            for (int q = 0; q < 4; q++) {
                float4 t4 = *(const float4*)(pp + q * 4);
                v[q * 4 + 0] = t4.x; v[q * 4 + 1] = t4.y;
                v[q * 4 + 2] = t4.z; v[q * 4 + 3] = t4.w;
            }
        }
    }
    #pragma unroll
    for (int q2 = 0; q2 < 4; q2++) {
        uint32_t hi4[4], lo4[4];
        #pragma unroll
        for (int i = 0; i < 4; i++) {
            float f0 = v[q2 * 8 + i * 2]     * p;
            float f1 = v[q2 * 8 + i * 2 + 1] * p;
            uint32_t hb = pack_bf16(f0, f1);
            float fh0 = __uint_as_float(hb << 16);
            float fh1 = __uint_as_float(hb & 0xFFFF0000u);
            hi4[i] = hb;
            lo4[i] = pack_bf16(f0 - fh0, f1 - fh1);
        }
        int q = half * 4 + q2;
        STS128(sw128(buf, ar, q),         hi4[0], hi4[1], hi4[2], hi4[3]);
        STS128(sw128(buf + 16384, ar, q), lo4[0], lo4[1], lo4[2], lo4[3]);
    }
}

// one k16 math step for the current buffer
__device__ __forceinline__ void math_kh(uint32_t cb, int kh, int wm, int wn,
                                        int j, int rr, float acc[4][8][4])
{
    uint32_t afh[4][4], afl[4][4];
    #pragma unroll
    for (int t = 0; t < 4; t++) {
        int row = wm + t * 16 + ((j & 1) << 3) + rr;
        int q = kh * 2 + (j >> 1);
        LDSM4(afh[t], sw128(cb, row, q));
        LDSM4(afl[t], sw128(cb + 16384, row, q));
    }
    #pragma unroll
    for (int uh = 0; uh < 2; uh++) {
        uint32_t bfh[4][2], bfl[4][2];
        #pragma unroll
        for (int up = 0; up < 2; up++) {
            int u0 = uh * 4 + up * 2;
            int nrow = wn + u0 * 8 + ((j >> 1) << 3) + rr;
            int q = kh * 2 + (j & 1);
            uint32_t t4[4];
            LDSM4(t4, sw128(cb + 32768, nrow, q));
            bfh[up * 2][0] = t4[0]; bfh[up * 2][1] = t4[1];
            bfh[up * 2 + 1][0] = t4[2]; bfh[up * 2 + 1][1] = t4[3];
            LDSM4(t4, sw128(cb + 65536, nrow, q));
            bfl[up * 2][0] = t4[0]; bfl[up * 2][1] = t4[1];
            bfl[up * 2 + 1][0] = t4[2]; bfl[up * 2 + 1][1] = t4[3];
        }
        #pragma unroll
        for (int t = 0; t < 4; t++)
            #pragma unroll
            for (int uu = 0; uu < 4; uu++) {
                MMA_BF16(acc[t][uh * 4 + uu], afh[t], bfh[uu]);
                MMA_BF16(acc[t][uh * 4 + uu], afh[t], bfl[uu]);
                MMA_BF16(acc[t][uh * 4 + uu], afl[t], bfh[uu]);
            }
    }
}

__global__ __launch_bounds__(256, 1) void main_gemm(
    const float* __restrict__ x, float* __restrict__ out)
{
    extern __shared__ char smem[];
    const uint32_t sb = smem_to_u32(smem);
    const int tid = threadIdx.x;
    const int lane = tid & 31, w = tid >> 5;
    const int bm = blockIdx.y * 128;
    const int bn = blockIdx.x * 256;
    const int wm = (w & 1) * 64, wn = (w >> 1) * 64;

    float acc[4][8][4];
    #pragma unroll
    for (int t = 0; t < 4; t++)
        #pragma unroll
        for (int u = 0; u < 8; u++)
            #pragma unroll
            for (int c = 0; c < 4; c++) acc[t][u][c] = 0.f;

    // prologue: stage 0 into buffer 0
    cp_b_stage(sb, bn, 0, tid);
    CP_COMMIT();
    gen_a_stage(sb, x, bm, 0, tid);
    CP_WAIT0();
    __syncthreads();

    const int j = lane >> 3, rr = lane & 7;

    for (int s = 0; s < NSTG; s++) {
        const uint32_t cb = sb + (uint32_t)(s & 1) * BUFSTRIDE;
        const uint32_t nb = sb + (uint32_t)((s + 1) & 1) * BUFSTRIDE;
        const bool has_next = (s + 1 < NSTG);

        if (has_next) {
            cp_b_stage(nb, bn, s + 1, tid);
            CP_COMMIT();
        }

        math_kh(cb, 0, wm, wn, j, rr, acc);
        math_kh(cb, 1, wm, wn, j, rr, acc);

        if (has_next)
            gen_a_stage(nb, x, bm, s + 1, tid);

        math_kh(cb, 2, wm, wn, j, rr, acc);
        math_kh(cb, 3, wm, wn, j, rr, acc);

        if (has_next) CP_WAIT0();
        __syncthreads();
    }

    // epilogue
    #pragma unroll
    for (int t = 0; t < 4; t++) {
        int row0 = bm + wm + t * 16 + (lane >> 2);
        #pragma unroll
        for (int u = 0; u < 8; u++) {
            int col = bn + wn + u * 8 + (lane & 3) * 2;
            *(float2*)&out[(size_t)row0 * D_OUT + col] =
                make_float2(acc[t][u][0], acc[t][u][1]);
            *(float2*)&out[(size_t)(row0 + 8) * D_OUT + col] =
                make_float2(acc[t][u][2], acc[t][u][3]);
        }
    }
}

// ============================================================================
extern "C" void kernel_launch(void* const* d_in, const int* in_sizes, int n_in,
                              void* d_out, int out_size)
{
    const float* x  = (const float*)d_in[0];
    const float* Wy = (const float*)d_in[1];
    const float* by = (const float*)d_in[2];
    const float* Wd = (const float*)d_in[3];
    const float* bd = (const float*)d_in[4];
    float* out = (float*)d_out;

    cudaFuncSetAttribute(main_gemm, cudaFuncAttributeMaxDynamicSharedMemorySize,
                         GSMEM_TOTAL);

    transpose_split<<<dim3(KTOT / 64, D_OUT / 64), 256>>>(Wy);
    by_prep<<<D_OUT / 256, 256>>>(by);
    logits_kernel<<<dim3(256 / 64, B_DIM / 64), 256>>>(x, Wd, bd);
    power_kernel<<<B_DIM / 16, 256>>>();
    main_gemm<<<dim3(D_OUT / 256, B_DIM / 128), 256, GSMEM_TOTAL>>>(x, out);
}

// round 8
// speedup vs baseline: 1.0499x; 1.0499x over previous
#include <cuda_runtime.h>
#include <cuda_bf16.h>
#include <cstdint>

#define B_DIM 4096
#define N_CIT 16
#define D_IN  1024
#define D_OUT 1024
#define KTOT  (N_CIT * D_IN)       /* 16384 */
#define EPSV  0.01f

// ---------------- scratch (static device arrays; no cudaMalloc) -------------
__device__ float g_logits[B_DIM * 256];
__device__ float g_power [B_DIM * 16];
__device__ __nv_bfloat16 g_wt_hi[(size_t)D_OUT * KTOT];  // [o][k] K-major
__device__ __nv_bfloat16 g_wt_lo[(size_t)D_OUT * KTOT];
__device__ __nv_bfloat16 g_by_hi[(size_t)D_OUT * 32];    // [o][k] k 0..15 real, rest 0
__device__ __nv_bfloat16 g_by_lo[(size_t)D_OUT * 32];
__device__ __nv_bfloat16 g_wd_hi[256 * D_IN];            // [c][k] K-major, c = n*16+j
__device__ __nv_bfloat16 g_wd_lo[256 * D_IN];

// ---------------- helpers ----------------------------------------------------
__device__ __forceinline__ uint32_t smem_to_u32(const void* p) {
    uint32_t a;
    asm("{ .reg .u64 t; cvta.to.shared.u64 t, %1; cvt.u32.u64 %0, t; }" : "=r"(a) : "l"(p));
    return a;
}

// swizzled address inside a tile of 64B rows: granule q (0..3) of row
__device__ __forceinline__ uint32_t sw(uint32_t base, int row, int q) {
    return base + row * 64 + (((uint32_t)(q ^ ((row >> 1) & 3))) << 4);
}

// pack two floats as bf16x2 (f0 -> low half)
__device__ __forceinline__ uint32_t pack_bf16(float f0, float f1) {
    uint32_t r;
    asm("cvt.rn.bf16x2.f32 %0, %1, %2;" : "=r"(r) : "f"(f1), "f"(f0));
    return r;
}

#define CP_ASYNC16(dst, src) \
    asm volatile("cp.async.cg.shared.global [%0], [%1], 16;" :: "r"(dst), "l"(src) : "memory")
#define CP_COMMIT() asm volatile("cp.async.commit_group;" ::: "memory")
#define CP_WAIT0()  asm volatile("cp.async.wait_group 0;" ::: "memory")

#define LDSM4(r, addr) \
    asm volatile("ldmatrix.sync.aligned.m8n8.x4.shared.b16 {%0,%1,%2,%3}, [%4];" \
        : "=r"((r)[0]), "=r"((r)[1]), "=r"((r)[2]), "=r"((r)[3]) : "r"(addr))

#define MMA_BF16(d, a, b) \
    asm volatile("mma.sync.aligned.m16n8k16.row.col.f32.bf16.bf16.f32 " \
        "{%0,%1,%2,%3}, {%4,%5,%6,%7}, {%8,%9}, {%0,%1,%2,%3};" \
        : "+f"((d)[0]), "+f"((d)[1]), "+f"((d)[2]), "+f"((d)[3]) \
        : "r"((a)[0]), "r"((a)[1]), "r"((a)[2]), "r"((a)[3]), "r"((b)[0]), "r"((b)[1]))

#define STS128(addr, r0, r1, r2, r3) \
    asm volatile("st.shared.v4.b32 [%0], {%1,%2,%3,%4};" \
        :: "r"(addr), "r"(r0), "r"(r1), "r"(r2), "r"(r3) : "memory")

// ============================================================================
// Kernel 0a: transpose + hi/lo bf16 split: Wy[16384,1024] -> g_wt[1024][16384]
// ============================================================================
__global__ __launch_bounds__(256) void transpose_split(const float* __restrict__ Wy)
{
    __shared__ float T[64][65];
    const int k0 = blockIdx.x * 64;
    const int o0 = blockIdx.y * 64;
    const int tid = threadIdx.x;

    {
        int kr = tid >> 4, o4 = tid & 15;
        #pragma unroll
        for (int r = 0; r < 4; r++) {
            int k = kr + r * 16;
            float4 v = *(const float4*)&Wy[(size_t)(k0 + k) * D_OUT + o0 + o4 * 4];
            T[k][o4 * 4 + 0] = v.x;  T[k][o4 * 4 + 1] = v.y;
            T[k][o4 * 4 + 2] = v.z;  T[k][o4 * 4 + 3] = v.w;
        }
    }
    __syncthreads();

    {
        int o = tid >> 2, kq = tid & 3;
        uint32_t hi[8], lo[8];
        #pragma unroll
        for (int i = 0; i < 8; i++) {
            float a = T[kq * 16 + i * 2][o];
            float b = T[kq * 16 + i * 2 + 1][o];
            uint32_t h = pack_bf16(a, b);
            float fha = __uint_as_float(h << 16);
            float fhb = __uint_as_float(h & 0xFFFF0000u);
            hi[i] = h;
            lo[i] = pack_bf16(a - fha, b - fhb);
        }
        size_t dst = (size_t)(o0 + o) * KTOT + k0 + kq * 16;
        *(uint4*)&g_wt_hi[dst]     = make_uint4(hi[0], hi[1], hi[2], hi[3]);
        *(uint4*)&g_wt_hi[dst + 8] = make_uint4(hi[4], hi[5], hi[6], hi[7]);
        *(uint4*)&g_wt_lo[dst]     = make_uint4(lo[0], lo[1], lo[2], lo[3]);
        *(uint4*)&g_wt_lo[dst + 8] = make_uint4(lo[4], lo[5], lo[6], lo[7]);
    }
}

// ============================================================================
// Kernel 0b: by[16][1024] -> g_by[1024][32] bf16 hi/lo (k 16..31 zero)
// ============================================================================
__global__ __launch_bounds__(256) void by_prep(const float* __restrict__ by)
{
    int o = blockIdx.x * 256 + threadIdx.x;
    if (o >= D_OUT) return;
    #pragma unroll
    for (int kp = 0; kp < 8; kp++) {
        float a = by[(size_t)(kp * 2)     * D_OUT + o];
        float b = by[(size_t)(kp * 2 + 1) * D_OUT + o];
        uint32_t h = pack_bf16(a, b);
        float fha = __uint_as_float(h << 16);
        float fhb = __uint_as_float(h & 0xFFFF0000u);
        uint32_t l = pack_bf16(a - fha, b - fhb);
        *(uint32_t*)&g_by_hi[(size_t)o * 32 + kp * 2] = h;
        *(uint32_t*)&g_by_lo[(size_t)o * 32 + kp * 2] = l;
    }
    #pragma unroll
    for (int kp = 8; kp < 16; kp++) {
        *(uint32_t*)&g_by_hi[(size_t)o * 32 + kp * 2] = 0u;
        *(uint32_t*)&g_by_lo[(size_t)o * 32 + kp * 2] = 0u;
    }
}

// ============================================================================
// Kernel 0c: Wd[16][1024][16] -> g_wd[256][1024] bf16 hi/lo (c = n*16+j, K-major)
// ============================================================================
__global__ __launch_bounds__(256) void wd_prep(const float* __restrict__ Wd)
{
    const int c = blockIdx.x;          // 0..255
    const int n = c >> 4, j = c & 15;
    const int tid = threadIdx.x;
    const float* src = Wd + (size_t)n * (D_IN * 16) + j;
    int k = tid * 4;
    float a0 = src[(size_t)(k + 0) * 16];
    float a1 = src[(size_t)(k + 1) * 16];
    float a2 = src[(size_t)(k + 2) * 16];
    float a3 = src[(size_t)(k + 3) * 16];
    uint32_t h0 = pack_bf16(a0, a1);
    uint32_t h1 = pack_bf16(a2, a3);
    float f0 = __uint_as_float(h0 << 16);
    float f1 = __uint_as_float(h0 & 0xFFFF0000u);
    float f2 = __uint_as_float(h1 << 16);
    float f3 = __uint_as_float(h1 & 0xFFFF0000u);
    uint32_t l0 = pack_bf16(a0 - f0, a1 - f1);
    uint32_t l1 = pack_bf16(a2 - f2, a3 - f3);
    *(uint2*)&g_wd_hi[(size_t)c * D_IN + k] = make_uint2(h0, h1);
    *(uint2*)&g_wd_lo[(size_t)c * D_IN + k] = make_uint2(l0, l1);
}

// ============================================================================
// Kernel 1: logits via split-bf16 mma. Tile 128x256, K=1024, 32 stages.
// logits[b,c] = sum_k x[b,k]*WdF[k,c] + bd[c]
// ============================================================================
#define BUFSTRIDE 49152
#define GSMEM_TOTAL (2 * BUFSTRIDE)

__device__ __forceinline__ void cp_b_logits(uint32_t buf, int t, int tid)
{
    size_t off = ((size_t)tid * D_IN + (size_t)t * 32) * 2;
    const char* sh = (const char*)g_wd_hi + off;
    const char* sl = (const char*)g_wd_lo + off;
    uint32_t bh = buf + 16384, bl = buf + 32768;
    #pragma unroll
    for (int q = 0; q < 4; q++) {
        CP_ASYNC16(sw(bh, tid, q), sh + q * 16);
        CP_ASYNC16(sw(bl, tid, q), sl + q * 16);
    }
}

__device__ __forceinline__ void gen_a_logits(uint32_t buf, const float* __restrict__ x,
                                             int bm, int t, int tid)
{
    const int ar = tid >> 1;
    const int half = tid & 1;
    float v[16];
    const float* xp = x + (size_t)(bm + ar) * D_IN + t * 32 + half * 16;
    #pragma unroll
    for (int q = 0; q < 4; q++) {
        float4 t4 = *(const float4*)(xp + q * 4);
        v[q * 4 + 0] = t4.x; v[q * 4 + 1] = t4.y;
        v[q * 4 + 2] = t4.z; v[q * 4 + 3] = t4.w;
    }
    #pragma unroll
    for (int q2 = 0; q2 < 2; q2++) {
        uint32_t hi4[4], lo4[4];
        #pragma unroll
        for (int i = 0; i < 4; i++) {
            float f0 = v[q2 * 8 + i * 2];
            float f1 = v[q2 * 8 + i * 2 + 1];
            uint32_t hb = pack_bf16(f0, f1);
            float fh0 = __uint_as_float(hb << 16);
            float fh1 = __uint_as_float(hb & 0xFFFF0000u);
            hi4[i] = hb;
            lo4[i] = pack_bf16(f0 - fh0, f1 - fh1);
        }
        int q = half * 2 + q2;
        STS128(sw(buf, ar, q),        hi4[0], hi4[1], hi4[2], hi4[3]);
        STS128(sw(buf + 8192, ar, q), lo4[0], lo4[1], lo4[2], lo4[3]);
    }
}

// one k16 math step (shared by logits_mma and main_gemm)
__device__ __forceinline__ void math_kh(uint32_t cb, int kh, int wm, int wn,
                                        int j, int rr, float acc[4][8][4])
{
    uint32_t afh[4][4], afl[4][4];
    #pragma unroll
    for (int t = 0; t < 4; t++) {
        int row = wm + t * 16 + ((j & 1) << 3) + rr;
        int q = kh * 2 + (j >> 1);
        LDSM4(afh[t], sw(cb, row, q));
        LDSM4(afl[t], sw(cb + 8192, row, q));
    }
    #pragma unroll
    for (int uh = 0; uh < 2; uh++) {
        uint32_t bfh[4][2], bfl[4][2];
        #pragma unroll
        for (int up = 0; up < 2; up++) {
            int u0 = uh * 4 + up * 2;
            int nrow = wn + u0 * 8 + ((j >> 1) << 3) + rr;
            int q = kh * 2 + (j & 1);
            uint32_t t4[4];
            LDSM4(t4, sw(cb + 16384, nrow, q));
            bfh[up * 2][0] = t4[0]; bfh[up * 2][1] = t4[1];
            bfh[up * 2 + 1][0] = t4[2]; bfh[up * 2 + 1][1] = t4[3];
            LDSM4(t4, sw(cb + 32768, nrow, q));
            bfl[up * 2][0] = t4[0]; bfl[up * 2][1] = t4[1];
            bfl[up * 2 + 1][0] = t4[2]; bfl[up * 2 + 1][1] = t4[3];
        }
        #pragma unroll
        for (int t = 0; t < 4; t++)
            #pragma unroll
            for (int uu = 0; uu < 4; uu++) {
                MMA_BF16(acc[t][uh * 4 + uu], afh[t], bfh[uu]);
                MMA_BF16(acc[t][uh * 4 + uu], afh[t], bfl[uu]);
                MMA_BF16(acc[t][uh * 4 + uu], afl[t], bfh[uu]);
            }
    }
}

__global__ __launch_bounds__(256, 1) void logits_mma(
    const float* __restrict__ x, const float* __restrict__ bd)
{
    extern __shared__ char smem[];
    const uint32_t sb = smem_to_u32(smem);
    const int tid = threadIdx.x;
    const int lane = tid & 31, w = tid >> 5;
    const int bm = blockIdx.y * 128;
    const int wm = (w & 1) * 64, wn = (w >> 1) * 64;

    float acc[4][8][4];
    #pragma unroll
    for (int t = 0; t < 4; t++)
        #pragma unroll
        for (int u = 0; u < 8; u++)
            #pragma unroll
            for (int c = 0; c < 4; c++) acc[t][u][c] = 0.f;

    cp_b_logits(sb, 0, tid);
    CP_COMMIT();
    gen_a_logits(sb, x, bm, 0, tid);
    CP_WAIT0();
    __syncthreads();

    const int j = lane >> 3, rr = lane & 7;

    for (int s = 0; s < 32; s++) {
        const uint32_t cb = sb + (uint32_t)(s & 1) * BUFSTRIDE;
        const uint32_t nb = sb + (uint32_t)((s + 1) & 1) * BUFSTRIDE;
        const bool has_next = (s + 1 < 32);

        if (has_next) {
            cp_b_logits(nb, s + 1, tid);
            CP_COMMIT();
        }
        math_kh(cb, 0, wm, wn, j, rr, acc);
        if (has_next)
            gen_a_logits(nb, x, bm, s + 1, tid);
        math_kh(cb, 1, wm, wn, j, rr, acc);
        if (has_next) CP_WAIT0();
        __syncthreads();
    }

    // epilogue: + bd[c], write g_logits
    #pragma unroll
    for (int t = 0; t < 4; t++) {
        int row0 = bm + wm + t * 16 + (lane >> 2);
        #pragma unroll
        for (int u = 0; u < 8; u++) {
            int col = wn + u * 8 + (lane & 3) * 2;
            float b0 = __ldg(bd + col), b1 = __ldg(bd + col + 1);
            *(float2*)&g_logits[(size_t)row0 * 256 + col] =
                make_float2(acc[t][u][0] + b0, acc[t][u][1] + b1);
            *(float2*)&g_logits[(size_t)(row0 + 8) * 256 + col] =
                make_float2(acc[t][u][2] + b0, acc[t][u][3] + b1);
        }
    }
}

// ============================================================================
// Kernel 2: warp-parallel softmax + 16x16 solve. 16 lanes per batch.
// ============================================================================
__global__ __launch_bounds__(256) void power_kernel()
{
    const int tid = threadIdx.x;
    const int lane = tid & 31;
    const int l16 = lane & 15;
    const int b = blockIdx.x * 16 + (tid >> 4);
    const float ome = 1.f - EPSV;

    float d[16];
    {
        const float* lg = g_logits + (size_t)b * 256 + l16 * 16;
        #pragma unroll
        for (int q = 0; q < 4; q++) {
            float4 t = *(const float4*)(lg + q * 4);
            d[q * 4 + 0] = t.x; d[q * 4 + 1] = t.y;
            d[q * 4 + 2] = t.z; d[q * 4 + 3] = t.w;
        }
        float mx = d[0];
        #pragma unroll
        for (int j = 1; j < 16; j++) mx = fmaxf(mx, d[j]);
        float s = 0.f;
        #pragma unroll
        for (int j = 0; j < 16; j++) { d[j] = expf(d[j] - mx); s += d[j]; }
        float inv = 1.f / s;
        #pragma unroll
        for (int j = 0; j < 16; j++) d[j] *= inv;
    }

    #pragma unroll
    for (int m = 1; m < 16; m <<= 1) {
        float u[16];
        #pragma unroll
        for (int i = 0; i < 16; i++)
            u[i] = __shfl_xor_sync(0xffffffffu, d[i ^ m], m);
        #pragma unroll
        for (int i = 0; i < 16; i++)
            if ((i & m) != (l16 & m)) d[i] = u[i];
    }

    float diag = 0.f;
    #pragma unroll
    for (int i = 0; i < 16; i++)
        if (i == l16) diag = d[i];

    float row[17];
    #pragma unroll
    for (int n = 0; n < 16; n++)
        row[n] = (n == l16) ? 1.f : -ome * d[n];
    row[16] = 1.f;

    #pragma unroll
    for (int p = 0; p < 16; p++) {
        float pivot = __shfl_sync(0xffffffffu, row[p], p, 16);
        float inv = 1.f / pivot;
        float f = row[p];
        #pragma unroll
        for (int c = p; c < 17; c++) {
            float pc = __shfl_sync(0xffffffffu, row[c], p, 16) * inv;
            if (l16 == p)      row[c] = pc;
            else if (l16 > p)  row[c] -= f * pc;
        }
    }

    float s = row[16];
    float z = 0.f;
    #pragma unroll
    for (int r = 15; r >= 0; r--) {
        float zr = __shfl_sync(0xffffffffu, s, r, 16);
        if (l16 == r) z = zr;
        if (l16 < r)  s -= row[r] * zr;
    }

    float zs = z;
    #pragma unroll
    for (int m = 8; m >= 1; m >>= 1)
        zs += __shfl_xor_sync(0xffffffffu, zs, m);
    float z16 = 1.f + EPSV * zs;
    float add = z16 * (1.f / 16.f) - (1.f / 16.f);
    g_power[(size_t)b * 16 + l16] = z * ome * diag + add;
}

// ============================================================================
// Kernel 3: mma.sync split-bf16 GEMM. CTA tile 128x256, K-chunk 32, 2 buffers.
// (round-6 best configuration)
// ============================================================================
#define NSTG 513

__device__ __forceinline__ void cp_b_stage(uint32_t buf, int bn, int t, int tid)
{
    uint32_t bh = buf + 16384, bl = buf + 32768;
    const char *sh, *sl;
    if (t < 512) {
        size_t off = ((size_t)(bn + tid) * KTOT +
                      (size_t)(t & 15) * 1024 + (size_t)(t >> 4) * 32) * 2;
        sh = (const char*)g_wt_hi + off;
        sl = (const char*)g_wt_lo + off;
    } else {
        size_t off = (size_t)(bn + tid) * 64;
        sh = (const char*)g_by_hi + off;
        sl = (const char*)g_by_lo + off;
    }
    #pragma unroll
    for (int q = 0; q < 4; q++) {
        CP_ASYNC16(sw(bh, tid, q), sh + q * 16);
        CP_ASYNC16(sw(bl, tid, q), sl + q * 16);
    }
}

__device__ __forceinline__ void gen_a_stage(uint32_t buf, const float* __restrict__ x,
                                            int bm, int t, int tid)
{
    const int ar = tid >> 1;
    const int ah_half = tid & 1;
    float v[16];
    float p;
    if (t < 512) {
        const int n = t & 15, o = t >> 4;
        p = g_power[(size_t)(bm + ar) * 16 + n];
        const float* xp = x + (size_t)(bm + ar) * D_IN + o * 32 + ah_half * 16;
        #pragma unroll
        for (int q = 0; q < 4; q++) {
            float4 t4 = *(const float4*)(xp + q * 4);
            v[q * 4 + 0] = t4.x; v[q * 4 + 1] = t4.y;
            v[q * 4 + 2] = t4.z; v[q * 4 + 3] = t4.w;
        }
    } else {
        p = 1.f;
        if (ah_half == 0) {
            const float* pp = &g_power[(size_t)(bm + ar) * 16];
            #pragma unroll
            for (int q = 0; q < 4; q++) {
                float4 t4 = *(const float4*)(pp + q * 4);
                v[q * 4 + 0] = t4.x; v[q * 4 + 1] = t4.y;
                v[q * 4 + 2] = t4.z; v[q * 4 + 3] = t4.w;
            }
        } else {
            #pragma unroll
            for (int q = 0; q < 16; q++) v[q] = 0.f;
        }
    }
    #pragma unroll
    for (int q2 = 0; q2 < 2; q2++) {
        uint32_t hi4[4], lo4[4];
        #pragma unroll
        for (int i = 0; i < 4; i++) {
            float f0 = v[q2 * 8 + i * 2]     * p;
            float f1 = v[q2 * 8 + i * 2 + 1] * p;
            uint32_t hb = pack_bf16(f0, f1);
            float fh0 = __uint_as_float(hb << 16);
            float fh1 = __uint_as_float(hb & 0xFFFF0000u);
            hi4[i] = hb;
            lo4[i] = pack_bf16(f0 - fh0, f1 - fh1);
        }
        int q = ah_half * 2 + q2;
        STS128(sw(buf, ar, q),        hi4[0], hi4[1], hi4[2], hi4[3]);
        STS128(sw(buf + 8192, ar, q), lo4[0], lo4[1], lo4[2], lo4[3]);
    }
}

__global__ __launch_bounds__(256, 1) void main_gemm(
    const float* __restrict__ x, float* __restrict__ out)
{
    extern __shared__ char smem[];
    const uint32_t sb = smem_to_u32(smem);
    const int tid = threadIdx.x;
    const int lane = tid & 31, w = tid >> 5;
    const int bm = blockIdx.y * 128;
    const int bn = blockIdx.x * 256;
    const int wm = (w & 1) * 64, wn = (w >> 1) * 64;

    float acc[4][8][4];
    #pragma unroll
    for (int t = 0; t < 4; t++)
        #pragma unroll
        for (int u = 0; u < 8; u++)
            #pragma unroll
            for (int c = 0; c < 4; c++) acc[t][u][c] = 0.f;

    cp_b_stage(sb, bn, 0, tid);
    CP_COMMIT();
    gen_a_stage(sb, x, bm, 0, tid);
    CP_WAIT0();
    __syncthreads();

    const int j = lane >> 3, rr = lane & 7;

    for (int s = 0; s < NSTG; s++) {
        const uint32_t cb = sb + (uint32_t)(s & 1) * BUFSTRIDE;
        const uint32_t nb = sb + (uint32_t)((s + 1) & 1) * BUFSTRIDE;
        const bool has_next = (s + 1 < NSTG);

        if (has_next) {
            cp_b_stage(nb, bn, s + 1, tid);
            CP_COMMIT();
        }
        math_kh(cb, 0, wm, wn, j, rr, acc);
        if (has_next)
            gen_a_stage(nb, x, bm, s + 1, tid);
        math_kh(cb, 1, wm, wn, j, rr, acc);
        if (has_next) CP_WAIT0();
        __syncthreads();
    }

    #pragma unroll
    for (int t = 0; t < 4; t++) {
        int row0 = bm + wm + t * 16 + (lane >> 2);
        #pragma unroll
        for (int u = 0; u < 8; u++) {
            int col = bn + wn + u * 8 + (lane & 3) * 2;
            *(float2*)&out[(size_t)row0 * D_OUT + col] =
                make_float2(acc[t][u][0], acc[t][u][1]);
            *(float2*)&out[(size_t)(row0 + 8) * D_OUT + col] =
                make_float2(acc[t][u][2], acc[t][u][3]);
        }
    }
}

// ============================================================================
extern "C" void kernel_launch(void* const* d_in, const int* in_sizes, int n_in,
                              void* d_out, int out_size)
{
    const float* x  = (const float*)d_in[0];
    const float* Wy = (const float*)d_in[1];
    const float* by = (const float*)d_in[2];
    const float* Wd = (const float*)d_in[3];
    const float* bd = (const float*)d_in[4];
    float* out = (float*)d_out;

    cudaFuncSetAttribute(main_gemm, cudaFuncAttributeMaxDynamicSharedMemorySize,
                         GSMEM_TOTAL);
    cudaFuncSetAttribute(logits_mma, cudaFuncAttributeMaxDynamicSharedMemorySize,
                         GSMEM_TOTAL);

    transpose_split<<<dim3(KTOT / 64, D_OUT / 64), 256>>>(Wy);
    by_prep<<<D_OUT / 256, 256>>>(by);
    wd_prep<<<256, 256>>>(Wd);
    logits_mma<<<dim3(1, B_DIM / 128), 256, GSMEM_TOTAL>>>(x, bd);
    power_kernel<<<B_DIM / 16, 256>>>();
    main_gemm<<<dim3(D_OUT / 256, B_DIM / 128), 256, GSMEM_TOTAL>>>(x, out);
}

// round 9
// speedup vs baseline: 1.1014x; 1.0490x over previous
#include <cuda_runtime.h>
#include <cuda_bf16.h>
#include <cstdint>

#define B_DIM 4096
#define N_CIT 16
#define D_IN  1024
#define D_OUT 1024
#define KTOT  (N_CIT * D_IN)       /* 16384 */
#define EPSV  0.01f
#define LSPLIT 4                   /* logits K splits */

// ---------------- scratch (static device arrays; no cudaMalloc) -------------
__device__ float g_lpart[LSPLIT * B_DIM * 256];
__device__ float g_power [B_DIM * 16];
__device__ __nv_bfloat16 g_wt_hi[(size_t)D_OUT * KTOT];  // [o][k] K-major
__device__ __nv_bfloat16 g_wt_lo[(size_t)D_OUT * KTOT];
__device__ __nv_bfloat16 g_by_hi[(size_t)D_OUT * 32];    // [o][k] k 0..15 real, rest 0
__device__ __nv_bfloat16 g_by_lo[(size_t)D_OUT * 32];
__device__ __nv_bfloat16 g_wd_hi[256 * D_IN];            // [c][k] K-major, c = n*16+j
__device__ __nv_bfloat16 g_wd_lo[256 * D_IN];

// ---------------- helpers ----------------------------------------------------
__device__ __forceinline__ uint32_t smem_to_u32(const void* p) {
    uint32_t a;
    asm("{ .reg .u64 t; cvta.to.shared.u64 t, %1; cvt.u32.u64 %0, t; }" : "=r"(a) : "l"(p));
    return a;
}

// swizzled address inside a tile of 64B rows: granule q (0..3) of row
__device__ __forceinline__ uint32_t sw(uint32_t base, int row, int q) {
    return base + row * 64 + (((uint32_t)(q ^ ((row >> 1) & 3))) << 4);
}

// pack two floats as bf16x2 (f0 -> low half)
__device__ __forceinline__ uint32_t pack_bf16(float f0, float f1) {
    uint32_t r;
    asm("cvt.rn.bf16x2.f32 %0, %1, %2;" : "=r"(r) : "f"(f1), "f"(f0));
    return r;
}

#define CP_ASYNC16(dst, src) \
    asm volatile("cp.async.cg.shared.global [%0], [%1], 16;" :: "r"(dst), "l"(src) : "memory")
#define CP_COMMIT() asm volatile("cp.async.commit_group;" ::: "memory")
#define CP_WAIT0()  asm volatile("cp.async.wait_group 0;" ::: "memory")

#define LDSM4(r, addr) \
    asm volatile("ldmatrix.sync.aligned.m8n8.x4.shared.b16 {%0,%1,%2,%3}, [%4];" \
        : "=r"((r)[0]), "=r"((r)[1]), "=r"((r)[2]), "=r"((r)[3]) : "r"(addr))

#define MMA_BF16(d, a, b) \
    asm volatile("mma.sync.aligned.m16n8k16.row.col.f32.bf16.bf16.f32 " \
        "{%0,%1,%2,%3}, {%4,%5,%6,%7}, {%8,%9}, {%0,%1,%2,%3};" \
        : "+f"((d)[0]), "+f"((d)[1]), "+f"((d)[2]), "+f"((d)[3]) \
        : "r"((a)[0]), "r"((a)[1]), "r"((a)[2]), "r"((a)[3]), "r"((b)[0]), "r"((b)[1]))

#define STS128(addr, r0, r1, r2, r3) \
    asm volatile("st.shared.v4.b32 [%0], {%1,%2,%3,%4};" \
        :: "r"(addr), "r"(r0), "r"(r1), "r"(r2), "r"(r3) : "memory")

// ============================================================================
// Kernel 0a: transpose + hi/lo bf16 split: Wy[16384,1024] -> g_wt[1024][16384]
// ============================================================================
__global__ __launch_bounds__(256) void transpose_split(const float* __restrict__ Wy)
{
    __shared__ float T[64][65];
    const int k0 = blockIdx.x * 64;
    const int o0 = blockIdx.y * 64;
    const int tid = threadIdx.x;

    {
        int kr = tid >> 4, o4 = tid & 15;
        #pragma unroll
        for (int r = 0; r < 4; r++) {
            int k = kr + r * 16;
            float4 v = *(const float4*)&Wy[(size_t)(k0 + k) * D_OUT + o0 + o4 * 4];
            T[k][o4 * 4 + 0] = v.x;  T[k][o4 * 4 + 1] = v.y;
            T[k][o4 * 4 + 2] = v.z;  T[k][o4 * 4 + 3] = v.w;
        }
    }
    __syncthreads();

    {
        int o = tid >> 2, kq = tid & 3;
        uint32_t hi[8], lo[8];
        #pragma unroll
        for (int i = 0; i < 8; i++) {
            float a = T[kq * 16 + i * 2][o];
            float b = T[kq * 16 + i * 2 + 1][o];
            uint32_t h = pack_bf16(a, b);
            float fha = __uint_as_float(h << 16);
            float fhb = __uint_as_float(h & 0xFFFF0000u);
            hi[i] = h;
            lo[i] = pack_bf16(a - fha, b - fhb);
        }
        size_t dst = (size_t)(o0 + o) * KTOT + k0 + kq * 16;
        *(uint4*)&g_wt_hi[dst]     = make_uint4(hi[0], hi[1], hi[2], hi[3]);
        *(uint4*)&g_wt_hi[dst + 8] = make_uint4(hi[4], hi[5], hi[6], hi[7]);
        *(uint4*)&g_wt_lo[dst]     = make_uint4(lo[0], lo[1], lo[2], lo[3]);
        *(uint4*)&g_wt_lo[dst + 8] = make_uint4(lo[4], lo[5], lo[6], lo[7]);
    }
}

// ============================================================================
// Kernel 0b: by[16][1024] -> g_by[1024][32] bf16 hi/lo (k 16..31 zero)
// ============================================================================
__global__ __launch_bounds__(256) void by_prep(const float* __restrict__ by)
{
    int o = blockIdx.x * 256 + threadIdx.x;
    if (o >= D_OUT) return;
    #pragma unroll
    for (int kp = 0; kp < 8; kp++) {
        float a = by[(size_t)(kp * 2)     * D_OUT + o];
        float b = by[(size_t)(kp * 2 + 1) * D_OUT + o];
        uint32_t h = pack_bf16(a, b);
        float fha = __uint_as_float(h << 16);
        float fhb = __uint_as_float(h & 0xFFFF0000u);
        uint32_t l = pack_bf16(a - fha, b - fhb);
        *(uint32_t*)&g_by_hi[(size_t)o * 32 + kp * 2] = h;
        *(uint32_t*)&g_by_lo[(size_t)o * 32 + kp * 2] = l;
    }
    #pragma unroll
    for (int kp = 8; kp < 16; kp++) {
        *(uint32_t*)&g_by_hi[(size_t)o * 32 + kp * 2] = 0u;
        *(uint32_t*)&g_by_lo[(size_t)o * 32 + kp * 2] = 0u;
    }
}

// ============================================================================
// Kernel 0c: Wd[16][1024][16] -> g_wd[256][1024] bf16 hi/lo (c = n*16+j, K-major)
// ============================================================================
__global__ __launch_bounds__(256) void wd_prep(const float* __restrict__ Wd)
{
    const int c = blockIdx.x;          // 0..255
    const int n = c >> 4, j = c & 15;
    const int tid = threadIdx.x;
    const float* src = Wd + (size_t)n * (D_IN * 16) + j;
    int k = tid * 4;
    float a0 = src[(size_t)(k + 0) * 16];
    float a1 = src[(size_t)(k + 1) * 16];
    float a2 = src[(size_t)(k + 2) * 16];
    float a3 = src[(size_t)(k + 3) * 16];
    uint32_t h0 = pack_bf16(a0, a1);
    uint32_t h1 = pack_bf16(a2, a3);
    float f0 = __uint_as_float(h0 << 16);
    float f1 = __uint_as_float(h0 & 0xFFFF0000u);
    float f2 = __uint_as_float(h1 << 16);
    float f3 = __uint_as_float(h1 & 0xFFFF0000u);
    uint32_t l0 = pack_bf16(a0 - f0, a1 - f1);
    uint32_t l1 = pack_bf16(a2 - f2, a3 - f3);
    *(uint2*)&g_wd_hi[(size_t)c * D_IN + k] = make_uint2(h0, h1);
    *(uint2*)&g_wd_lo[(size_t)c * D_IN + k] = make_uint2(l0, l1);
}

// ============================================================================
// shared math: one k16 step; pass-major MMA order (same-acc reuse distance 16)
// ============================================================================
__device__ __forceinline__ void math_kh(uint32_t cb, int kh, int wm, int wn,
                                        int j, int rr, float acc[4][8][4])
{
    uint32_t afh[4][4], afl[4][4];
    #pragma unroll
    for (int t = 0; t < 4; t++) {
        int row = wm + t * 16 + ((j & 1) << 3) + rr;
        int q = kh * 2 + (j >> 1);
        LDSM4(afh[t], sw(cb, row, q));
        LDSM4(afl[t], sw(cb + 8192, row, q));
    }
    #pragma unroll
    for (int uh = 0; uh < 2; uh++) {
        uint32_t bfh[4][2], bfl[4][2];
        #pragma unroll
        for (int up = 0; up < 2; up++) {
            int u0 = uh * 4 + up * 2;
            int nrow = wn + u0 * 8 + ((j >> 1) << 3) + rr;
            int q = kh * 2 + (j & 1);
            uint32_t t4[4];
            LDSM4(t4, sw(cb + 16384, nrow, q));
            bfh[up * 2][0] = t4[0]; bfh[up * 2][1] = t4[1];
            bfh[up * 2 + 1][0] = t4[2]; bfh[up * 2 + 1][1] = t4[3];
            LDSM4(t4, sw(cb + 32768, nrow, q));
            bfl[up * 2][0] = t4[0]; bfl[up * 2][1] = t4[1];
            bfl[up * 2 + 1][0] = t4[2]; bfl[up * 2 + 1][1] = t4[3];
        }
        // pass-major: hh, then h*lo, then lo*h — 16 independent MMAs per pass
        #pragma unroll
        for (int t = 0; t < 4; t++)
            #pragma unroll
            for (int uu = 0; uu < 4; uu++)
                MMA_BF16(acc[t][uh * 4 + uu], afh[t], bfh[uu]);
        #pragma unroll
        for (int t = 0; t < 4; t++)
            #pragma unroll
            for (int uu = 0; uu < 4; uu++)
                MMA_BF16(acc[t][uh * 4 + uu], afh[t], bfl[uu]);
        #pragma unroll
        for (int t = 0; t < 4; t++)
            #pragma unroll
            for (int uu = 0; uu < 4; uu++)
                MMA_BF16(acc[t][uh * 4 + uu], afl[t], bfh[uu]);
    }
}

// ============================================================================
// Kernel 1: logits partials via split-bf16 mma, split-K over 4 CTab groups.
// Each CTA: 128 batches x 256 cols, K = 256 (8 stages of 32).
// ============================================================================
#define BUFSTRIDE 49152
#define GSMEM_TOTAL (2 * BUFSTRIDE)
#define LSTG (D_IN / 32 / LSPLIT)   /* 8 stages per split */

__device__ __forceinline__ void cp_b_logits(uint32_t buf, int kc, int tid)
{
    size_t off = ((size_t)tid * D_IN + (size_t)kc * 32) * 2;
    const char* sh = (const char*)g_wd_hi + off;
    const char* sl = (const char*)g_wd_lo + off;
    uint32_t bh = buf + 16384, bl = buf + 32768;
    #pragma unroll
    for (int q = 0; q < 4; q++) {
        CP_ASYNC16(sw(bh, tid, q), sh + q * 16);
        CP_ASYNC16(sw(bl, tid, q), sl + q * 16);
    }
}

__device__ __forceinline__ void gen_a_logits(uint32_t buf, const float* __restrict__ x,
                                             int bm, int kc, int tid)
{
    const int ar = tid >> 1;
    const int half = tid & 1;
    float v[16];
    const float* xp = x + (size_t)(bm + ar) * D_IN + kc * 32 + half * 16;
    #pragma unroll
    for (int q = 0; q < 4; q++) {
        float4 t4 = *(const float4*)(xp + q * 4);
        v[q * 4 + 0] = t4.x; v[q * 4 + 1] = t4.y;
        v[q * 4 + 2] = t4.z; v[q * 4 + 3] = t4.w;
    }
    #pragma unroll
    for (int q2 = 0; q2 < 2; q2++) {
        uint32_t hi4[4], lo4[4];
        #pragma unroll
        for (int i = 0; i < 4; i++) {
            float f0 = v[q2 * 8 + i * 2];
            float f1 = v[q2 * 8 + i * 2 + 1];
            uint32_t hb = pack_bf16(f0, f1);
            float fh0 = __uint_as_float(hb << 16);
            float fh1 = __uint_as_float(hb & 0xFFFF0000u);
            hi4[i] = hb;
            lo4[i] = pack_bf16(f0 - fh0, f1 - fh1);
        }
        int q = half * 2 + q2;
        STS128(sw(buf, ar, q),        hi4[0], hi4[1], hi4[2], hi4[3]);
        STS128(sw(buf + 8192, ar, q), lo4[0], lo4[1], lo4[2], lo4[3]);
    }
}

__global__ __launch_bounds__(256, 1) void logits_mma(const float* __restrict__ x)
{
    extern __shared__ char smem[];
    const uint32_t sb = smem_to_u32(smem);
    const int tid = threadIdx.x;
    const int lane = tid & 31, w = tid >> 5;
    const int ks = blockIdx.x;              // K split 0..3
    const int bm = blockIdx.y * 128;
    const int wm = (w & 1) * 64, wn = (w >> 1) * 64;
    const int kc0 = ks * LSTG;

    float acc[4][8][4];
    #pragma unroll
    for (int t = 0; t < 4; t++)
        #pragma unroll
        for (int u = 0; u < 8; u++)
            #pragma unroll
            for (int c = 0; c < 4; c++) acc[t][u][c] = 0.f;

    cp_b_logits(sb, kc0, tid);
    CP_COMMIT();
    gen_a_logits(sb, x, bm, kc0, tid);
    CP_WAIT0();
    __syncthreads();

    const int j = lane >> 3, rr = lane & 7;

    for (int s = 0; s < LSTG; s++) {
        const uint32_t cb = sb + (uint32_t)(s & 1) * BUFSTRIDE;
        const uint32_t nb = sb + (uint32_t)((s + 1) & 1) * BUFSTRIDE;
        const bool has_next = (s + 1 < LSTG);

        if (has_next) {
            cp_b_logits(nb, kc0 + s + 1, tid);
            CP_COMMIT();
        }
        math_kh(cb, 0, wm, wn, j, rr, acc);
        if (has_next)
            gen_a_logits(nb, x, bm, kc0 + s + 1, tid);
        math_kh(cb, 1, wm, wn, j, rr, acc);
        if (has_next) CP_WAIT0();
        __syncthreads();
    }

    float* lp = g_lpart + (size_t)ks * (B_DIM * 256);
    #pragma unroll
    for (int t = 0; t < 4; t++) {
        int row0 = bm + wm + t * 16 + (lane >> 2);
        #pragma unroll
        for (int u = 0; u < 8; u++) {
            int col = wn + u * 8 + (lane & 3) * 2;
            *(float2*)&lp[(size_t)row0 * 256 + col] =
                make_float2(acc[t][u][0], acc[t][u][1]);
            *(float2*)&lp[(size_t)(row0 + 8) * 256 + col] =
                make_float2(acc[t][u][2], acc[t][u][3]);
        }
    }
}

// ============================================================================
// Kernel 2: sum partials + bd, softmax + 16x16 solve. 16 lanes per batch.
// ============================================================================
__global__ __launch_bounds__(256) void power_kernel(const float* __restrict__ bd)
{
    const int tid = threadIdx.x;
    const int lane = tid & 31;
    const int l16 = lane & 15;
    const int b = blockIdx.x * 16 + (tid >> 4);
    const float ome = 1.f - EPSV;

    float d[16];
    {
        size_t base = (size_t)b * 256 + l16 * 16;
        #pragma unroll
        for (int q = 0; q < 4; q++) {
            float4 t0 = *(const float4*)(g_lpart + base + q * 4);
            float4 t1 = *(const float4*)(g_lpart + (size_t)1 * B_DIM * 256 + base + q * 4);
            float4 t2 = *(const float4*)(g_lpart + (size_t)2 * B_DIM * 256 + base + q * 4);
            float4 t3 = *(const float4*)(g_lpart + (size_t)3 * B_DIM * 256 + base + q * 4);
            float4 bb = *(const float4*)(bd + l16 * 16 + q * 4);
            d[q * 4 + 0] = t0.x + t1.x + t2.x + t3.x + bb.x;
            d[q * 4 + 1] = t0.y + t1.y + t2.y + t3.y + bb.y;
            d[q * 4 + 2] = t0.z + t1.z + t2.z + t3.z + bb.z;
            d[q * 4 + 3] = t0.w + t1.w + t2.w + t3.w + bb.w;
        }
        float mx = d[0];
        #pragma unroll
        for (int j = 1; j < 16; j++) mx = fmaxf(mx, d[j]);
        float s = 0.f;
        #pragma unroll
        for (int j = 0; j < 16; j++) { d[j] = expf(d[j] - mx); s += d[j]; }
        float inv = 1.f / s;
        #pragma unroll
        for (int j = 0; j < 16; j++) d[j] *= inv;
    }

    #pragma unroll
    for (int m = 1; m < 16; m <<= 1) {
        float u[16];
        #pragma unroll
        for (int i = 0; i < 16; i++)
            u[i] = __shfl_xor_sync(0xffffffffu, d[i ^ m], m);
        #pragma unroll
        for (int i = 0; i < 16; i++)
            if ((i & m) != (l16 & m)) d[i] = u[i];
    }

    float diag = 0.f;
    #pragma unroll
    for (int i = 0; i < 16; i++)
        if (i == l16) diag = d[i];

    float row[17];
    #pragma unroll
    for (int n = 0; n < 16; n++)
        row[n] = (n == l16) ? 1.f : -ome * d[n];
    row[16] = 1.f;

    #pragma unroll
    for (int p = 0; p < 16; p++) {
        float pivot = __shfl_sync(0xffffffffu, row[p], p, 16);
        float inv = 1.f / pivot;
        float f = row[p];
        #pragma unroll
        for (int c = p; c < 17; c++) {
            float pc = __shfl_sync(0xffffffffu, row[c], p, 16) * inv;
            if (l16 == p)      row[c] = pc;
            else if (l16 > p)  row[c] -= f * pc;
        }
    }

    float s = row[16];
    float z = 0.f;
    #pragma unroll
    for (int r = 15; r >= 0; r--) {
        float zr = __shfl_sync(0xffffffffu, s, r, 16);
        if (l16 == r) z = zr;
        if (l16 < r)  s -= row[r] * zr;
    }

    float zs = z;
    #pragma unroll
    for (int m = 8; m >= 1; m >>= 1)
        zs += __shfl_xor_sync(0xffffffffu, zs, m);
    float z16 = 1.f + EPSV * zs;
    float add = z16 * (1.f / 16.f) - (1.f / 16.f);
    g_power[(size_t)b * 16 + l16] = z * ome * diag + add;
}

// ============================================================================
// Kernel 3: mma.sync split-bf16 GEMM. CTA tile 128x256, K-chunk 32, 2 buffers.
// ============================================================================
#define NSTG 513

__device__ __forceinline__ void cp_b_stage(uint32_t buf, int bn, int t, int tid)
{
    uint32_t bh = buf + 16384, bl = buf + 32768;
    const char *sh, *sl;
    if (t < 512) {
        size_t off = ((size_t)(bn + tid) * KTOT +
                      (size_t)(t & 15) * 1024 + (size_t)(t >> 4) * 32) * 2;
        sh = (const char*)g_wt_hi + off;
        sl = (const char*)g_wt_lo + off;
    } else {
        size_t off = (size_t)(bn + tid) * 64;
        sh = (const char*)g_by_hi + off;
        sl = (const char*)g_by_lo + off;
    }
    #pragma unroll
    for (int q = 0; q < 4; q++) {
        CP_ASYNC16(sw(bh, tid, q), sh + q * 16);
        CP_ASYNC16(sw(bl, tid, q), sl + q * 16);
    }
}

__device__ __forceinline__ void gen_a_stage(uint32_t buf, const float* __restrict__ x,
                                            int bm, int t, int tid)
{
    const int ar = tid >> 1;
    const int ah_half = tid & 1;
    float v[16];
    float p;
    if (t < 512) {
        const int n = t & 15, o = t >> 4;
        p = g_power[(size_t)(bm + ar) * 16 + n];
        const float* xp = x + (size_t)(bm + ar) * D_IN + o * 32 + ah_half * 16;
        #pragma unroll
        for (int q = 0; q < 4; q++) {
            float4 t4 = *(const float4*)(xp + q * 4);
            v[q * 4 + 0] = t4.x; v[q * 4 + 1] = t4.y;
            v[q * 4 + 2] = t4.z; v[q * 4 + 3] = t4.w;
        }
    } else {
        p = 1.f;
        if (ah_half == 0) {
            const float* pp = &g_power[(size_t)(bm + ar) * 16];
            #pragma unroll
            for (int q = 0; q < 4; q++) {
                float4 t4 = *(const float4*)(pp + q * 4);
                v[q * 4 + 0] = t4.x; v[q * 4 + 1] = t4.y;
                v[q * 4 + 2] = t4.z; v[q * 4 + 3] = t4.w;
            }
        } else {
            #pragma unroll
            for (int q = 0; q < 16; q++) v[q] = 0.f;
        }
    }
    #pragma unroll
    for (int q2 = 0; q2 < 2; q2++) {
        uint32_t hi4[4], lo4[4];
        #pragma unroll
        for (int i = 0; i < 4; i++) {
            float f0 = v[q2 * 8 + i * 2]     * p;
            float f1 = v[q2 * 8 + i * 2 + 1] * p;
            uint32_t hb = pack_bf16(f0, f1);
            float fh0 = __uint_as_float(hb << 16);
            float fh1 = __uint_as_float(hb & 0xFFFF0000u);
            hi4[i] = hb;
            lo4[i] = pack_bf16(f0 - fh0, f1 - fh1);
        }
        int q = ah_half * 2 + q2;
        STS128(sw(buf, ar, q),        hi4[0], hi4[1], hi4[2], hi4[3]);
        STS128(sw(buf + 8192, ar, q), lo4[0], lo4[1], lo4[2], lo4[3]);
    }
}

__global__ __launch_bounds__(256, 1) void main_gemm(
    const float* __restrict__ x, float* __restrict__ out)
{
    extern __shared__ char smem[];
    const uint32_t sb = smem_to_u32(smem);
    const int tid = threadIdx.x;
    const int lane = tid & 31, w = tid >> 5;
    const int bm = blockIdx.y * 128;
    const int bn = blockIdx.x * 256;
    const int wm = (w & 1) * 64, wn = (w >> 1) * 64;

    float acc[4][8][4];
    #pragma unroll
    for (int t = 0; t < 4; t++)
        #pragma unroll
        for (int u = 0; u < 8; u++)
            #pragma unroll
            for (int c = 0; c < 4; c++) acc[t][u][c] = 0.f;

    cp_b_stage(sb, bn, 0, tid);
    CP_COMMIT();
    gen_a_stage(sb, x, bm, 0, tid);
    CP_WAIT0();
    __syncthreads();

    const int j = lane >> 3, rr = lane & 7;

    for (int s = 0; s < NSTG; s++) {
        const uint32_t cb = sb + (uint32_t)(s & 1) * BUFSTRIDE;
        const uint32_t nb = sb + (uint32_t)((s + 1) & 1) * BUFSTRIDE;
        const bool has_next = (s + 1 < NSTG);

        if (has_next) {
            cp_b_stage(nb, bn, s + 1, tid);
            CP_COMMIT();
        }
        math_kh(cb, 0, wm, wn, j, rr, acc);
        if (has_next)
            gen_a_stage(nb, x, bm, s + 1, tid);
        math_kh(cb, 1, wm, wn, j, rr, acc);
        if (has_next) CP_WAIT0();
        __syncthreads();
    }

    #pragma unroll
    for (int t = 0; t < 4; t++) {
        int row0 = bm + wm + t * 16 + (lane >> 2);
        #pragma unroll
        for (int u = 0; u < 8; u++) {
            int col = bn + wn + u * 8 + (lane & 3) * 2;
            *(float2*)&out[(size_t)row0 * D_OUT + col] =
                make_float2(acc[t][u][0], acc[t][u][1]);
            *(float2*)&out[(size_t)(row0 + 8) * D_OUT + col] =
                make_float2(acc[t][u][2], acc[t][u][3]);
        }
    }
}

// ============================================================================
extern "C" void kernel_launch(void* const* d_in, const int* in_sizes, int n_in,
                              void* d_out, int out_size)
{
    const float* x  = (const float*)d_in[0];
    const float* Wy = (const float*)d_in[1];
    const float* by = (const float*)d_in[2];
    const float* Wd = (const float*)d_in[3];
    const float* bd = (const float*)d_in[4];
    float* out = (float*)d_out;

    cudaFuncSetAttribute(main_gemm, cudaFuncAttributeMaxDynamicSharedMemorySize,
                         GSMEM_TOTAL);
    cudaFuncSetAttribute(logits_mma, cudaFuncAttributeMaxDynamicSharedMemorySize,
                         GSMEM_TOTAL);

    transpose_split<<<dim3(KTOT / 64, D_OUT / 64), 256>>>(Wy);
    by_prep<<<D_OUT / 256, 256>>>(by);
    wd_prep<<<256, 256>>>(Wd);
    logits_mma<<<dim3(LSPLIT, B_DIM / 128), 256, GSMEM_TOTAL>>>(x);
    power_kernel<<<B_DIM / 16, 256>>>(bd);
    main_gemm<<<dim3(D_OUT / 256, B_DIM / 128), 256, GSMEM_TOTAL>>>(x, out);
}